// round 1
// baseline (speedup 1.0000x reference)
#include <cuda_runtime.h>
#include <cuda_bf16.h>
#include <cstdint>

// Problem constants (fixed by the dataset)
#define S_TOK   32768
#define HID     1280
#define NHEAD   16
#define DHEAD   80
#define WIN     64
#define NWIN    (S_TOK / WIN)          // 512
#define N_QKV   (3 * HID)              // 3840

// Scratch (allocation-free rule: __device__ globals)
__device__ float g_qkv[(size_t)S_TOK * N_QKV];   // [S, 3840] fp32
__device__ float g_attn[(size_t)S_TOK * HID];    // [S, 1280] fp32

// ---------------------------------------------------------------------------
// TF32 tensor-core GEMM: C[M,N] = A[M,K] @ B[K,N] + bias[N]
// A,B,C row-major fp32. M%128==0, N%128==0, K%32==0.
// Block tile 128x128x32, 256 threads (8 warps: 4 along M x 2 along N),
// warp tile 32x64 via m16n8k8 tf32 mma (2 x 8 subtiles).
// ---------------------------------------------------------------------------
#define BM 128
#define BN 128
#define BK 32

__device__ __forceinline__ uint32_t f2tf32(float x) {
    uint32_t r;
    asm volatile("cvt.rna.tf32.f32 %0, %1;" : "=r"(r) : "f"(x));
    return r;
}

__global__ __launch_bounds__(256, 2)
void gemm_tf32(const float* __restrict__ A, const float* __restrict__ B,
               const float* __restrict__ bias, float* __restrict__ C,
               int M, int N, int K)
{
    __shared__ float As[BM][BK + 4];   // pad 4 keeps float4 alignment, kills conflicts
    __shared__ float Bs[BK][BN + 4];

    const int tid  = threadIdx.x;
    const int warp = tid >> 5;
    const int lane = tid & 31;
    const int g = lane >> 2;      // group id 0..7
    const int t = lane & 3;       // thread-in-group 0..3

    const int wm = (warp & 3) * 32;   // warp M offset inside tile
    const int wn = (warp >> 2) * 64;  // warp N offset inside tile

    const int block_m = blockIdx.y * BM;
    const int block_n = blockIdx.x * BN;

    float acc[2][8][4];
    #pragma unroll
    for (int i = 0; i < 2; i++)
        #pragma unroll
        for (int j = 0; j < 8; j++)
            #pragma unroll
            for (int r = 0; r < 4; r++)
                acc[i][j][r] = 0.f;

    // staging layout
    const int a_row  = tid >> 3;          // 0..31
    const int a_col  = (tid & 7) * 4;     // 0..28
    const int b_row  = tid >> 5;          // 0..7
    const int b_col  = (tid & 31) * 4;    // 0..124

    for (int k0 = 0; k0 < K; k0 += BK) {
        // ---- stage A tile (128 x 32), convert to tf32 (RNA) ----
        #pragma unroll
        for (int i = 0; i < 4; i++) {
            const int r = a_row + i * 32;
            float4 v = *(const float4*)&A[(size_t)(block_m + r) * K + k0 + a_col];
            As[r][a_col + 0] = __uint_as_float(f2tf32(v.x));
            As[r][a_col + 1] = __uint_as_float(f2tf32(v.y));
            As[r][a_col + 2] = __uint_as_float(f2tf32(v.z));
            As[r][a_col + 3] = __uint_as_float(f2tf32(v.w));
        }
        // ---- stage B tile (32 x 128) ----
        #pragma unroll
        for (int i = 0; i < 4; i++) {
            const int r = b_row + i * 8;
            float4 v = *(const float4*)&B[(size_t)(k0 + r) * N + block_n + b_col];
            Bs[r][b_col + 0] = __uint_as_float(f2tf32(v.x));
            Bs[r][b_col + 1] = __uint_as_float(f2tf32(v.y));
            Bs[r][b_col + 2] = __uint_as_float(f2tf32(v.z));
            Bs[r][b_col + 3] = __uint_as_float(f2tf32(v.w));
        }
        __syncthreads();

        #pragma unroll
        for (int kk = 0; kk < BK; kk += 8) {
            uint32_t af[2][4];
            #pragma unroll
            for (int i = 0; i < 2; i++) {
                const int r0 = wm + i * 16;
                af[i][0] = __float_as_uint(As[r0 + g    ][kk + t    ]);
                af[i][1] = __float_as_uint(As[r0 + g + 8][kk + t    ]);
                af[i][2] = __float_as_uint(As[r0 + g    ][kk + t + 4]);
                af[i][3] = __float_as_uint(As[r0 + g + 8][kk + t + 4]);
            }
            uint32_t bf[8][2];
            #pragma unroll
            for (int j = 0; j < 8; j++) {
                const int c0 = wn + j * 8;
                bf[j][0] = __float_as_uint(Bs[kk + t    ][c0 + g]);
                bf[j][1] = __float_as_uint(Bs[kk + t + 4][c0 + g]);
            }
            #pragma unroll
            for (int i = 0; i < 2; i++)
                #pragma unroll
                for (int j = 0; j < 8; j++) {
                    asm volatile(
                        "mma.sync.aligned.m16n8k8.row.col.f32.tf32.tf32.f32 "
                        "{%0,%1,%2,%3}, {%4,%5,%6,%7}, {%8,%9}, {%0,%1,%2,%3};\n"
                        : "+f"(acc[i][j][0]), "+f"(acc[i][j][1]),
                          "+f"(acc[i][j][2]), "+f"(acc[i][j][3])
                        : "r"(af[i][0]), "r"(af[i][1]), "r"(af[i][2]), "r"(af[i][3]),
                          "r"(bf[j][0]), "r"(bf[j][1]));
                }
        }
        __syncthreads();
    }

    // ---- epilogue: bias + store ----
    #pragma unroll
    for (int i = 0; i < 2; i++) {
        #pragma unroll
        for (int j = 0; j < 8; j++) {
            const int r = block_m + wm + i * 16 + g;
            const int c = block_n + wn + j * 8 + t * 2;
            const float b0 = bias[c], b1 = bias[c + 1];
            C[(size_t)r       * N + c    ] = acc[i][j][0] + b0;
            C[(size_t)r       * N + c + 1] = acc[i][j][1] + b1;
            C[(size_t)(r + 8) * N + c    ] = acc[i][j][2] + b0;
            C[(size_t)(r + 8) * N + c + 1] = acc[i][j][3] + b1;
        }
    }
}

// ---------------------------------------------------------------------------
// Windowed attention, one block per (window, head). 128 threads.
// RoPE fused into q/k loads. fp32 throughout.
// Dynamic smem: qs[64*80] ks[64*80] vs[64*80] p[64*65]
// ---------------------------------------------------------------------------
#define P_STRIDE 65
#define ATTN_SMEM ((3 * 64 * 80 + 64 * P_STRIDE) * 4)

__global__ __launch_bounds__(128, 2)
void attn_win(const float* __restrict__ qkv,
              const float* __restrict__ cosp, const float* __restrict__ sinp,
              float* __restrict__ out)
{
    extern __shared__ float sh[];
    float* qs = sh;                 // [64][80]
    float* ks = sh + 64 * 80;       // [64][80]
    float* vs = sh + 2 * 64 * 80;   // [64][80]
    float* p  = sh + 3 * 64 * 80;   // [64][65]

    const int w = blockIdx.x >> 4;
    const int h = blockIdx.x & 15;
    const int tid = threadIdx.x;

    // ---- load q,k with fused RoPE; load v ----
    for (int idx = tid; idx < 64 * 40; idx += 128) {
        const int i = idx / 40;
        const int d = idx - i * 40;
        const int srow = w * WIN + i;
        const float c1 = cosp[srow * DHEAD + d];
        const float s1 = sinp[srow * DHEAD + d];
        const float c2 = cosp[srow * DHEAD + d + 40];
        const float s2 = sinp[srow * DHEAD + d + 40];
        const float* base = qkv + (size_t)srow * N_QKV + h * DHEAD;
        const float q1 = base[d],        q2 = base[d + 40];
        const float k1 = base[HID + d],  k2 = base[HID + d + 40];
        qs[i * 80 + d]      = q1 * c1 - q2 * s1;
        qs[i * 80 + d + 40] = q2 * c2 + q1 * s2;
        ks[i * 80 + d]      = k1 * c1 - k2 * s1;
        ks[i * 80 + d + 40] = k2 * c2 + k1 * s2;
    }
    for (int idx = tid; idx < 64 * 80; idx += 128) {
        const int i = idx / 80;
        const int d = idx - i * 80;
        vs[idx] = qkv[(size_t)(w * WIN + i) * N_QKV + 2 * HID + h * DHEAD + d];
    }
    __syncthreads();

    // ---- scores: 4x8 register tile per thread ----
    const int ti = tid >> 3;        // 0..15 -> rows i0 = ti*4
    const int tj = tid & 7;         // 0..7  -> cols j0 = tj*8
    const int i0 = ti * 4;
    const int j0 = tj * 8;
    float sc[4][8];
    #pragma unroll
    for (int r = 0; r < 4; r++)
        #pragma unroll
        for (int c = 0; c < 8; c++) sc[r][c] = 0.f;

    for (int d = 0; d < DHEAD; d++) {
        float qv[4], kv[8];
        #pragma unroll
        for (int r = 0; r < 4; r++) qv[r] = qs[(i0 + r) * 80 + d];
        #pragma unroll
        for (int c = 0; c < 8; c++) kv[c] = ks[(j0 + c) * 80 + d];
        #pragma unroll
        for (int r = 0; r < 4; r++)
            #pragma unroll
            for (int c = 0; c < 8; c++) sc[r][c] = fmaf(qv[r], kv[c], sc[r][c]);
    }
    const float scale = 0.11180339887498949f;   // 80^-0.5
    #pragma unroll
    for (int r = 0; r < 4; r++)
        #pragma unroll
        for (int c = 0; c < 8; c++)
            p[(i0 + r) * P_STRIDE + j0 + c] = sc[r][c] * scale;
    __syncthreads();

    // ---- softmax per row (threads 0..63) ----
    if (tid < 64) {
        float* row = p + tid * P_STRIDE;
        float m = -1e30f;
        #pragma unroll 8
        for (int j = 0; j < 64; j++) m = fmaxf(m, row[j]);
        float s = 0.f;
        #pragma unroll 8
        for (int j = 0; j < 64; j++) { float e = __expf(row[j] - m); row[j] = e; s += e; }
        const float inv = 1.f / s;
        #pragma unroll 8
        for (int j = 0; j < 64; j++) row[j] *= inv;
    }
    __syncthreads();

    // ---- O = P @ V : 4 rows x 10 cols per thread ----
    const int tc = tid & 7;         // 0..7 -> cols c0 = tc*10
    const int c0 = tc * 10;
    float o[4][10];
    #pragma unroll
    for (int r = 0; r < 4; r++)
        #pragma unroll
        for (int c = 0; c < 10; c++) o[r][c] = 0.f;

    for (int j = 0; j < 64; j++) {
        float pv[4], vv[10];
        #pragma unroll
        for (int r = 0; r < 4; r++) pv[r] = p[(i0 + r) * P_STRIDE + j];
        #pragma unroll
        for (int c = 0; c < 10; c++) vv[c] = vs[j * 80 + c0 + c];
        #pragma unroll
        for (int r = 0; r < 4; r++)
            #pragma unroll
            for (int c = 0; c < 10; c++) o[r][c] = fmaf(pv[r], vv[c], o[r][c]);
    }
    #pragma unroll
    for (int r = 0; r < 4; r++) {
        const size_t row = (size_t)(w * WIN + i0 + r) * HID + h * DHEAD + c0;
        #pragma unroll
        for (int c = 0; c < 10; c++) out[row + c] = o[r][c];
    }
}

// ---------------------------------------------------------------------------
extern "C" void kernel_launch(void* const* d_in, const int* in_sizes, int n_in,
                              void* d_out, int out_size)
{
    const float* x     = (const float*)d_in[0];
    const float* cosp  = (const float*)d_in[1];
    const float* sinp  = (const float*)d_in[2];
    // d_in[3] = cu_seqlens (uniform windows of 64 by construction; unused)
    const float* qkvW  = (const float*)d_in[4];
    const float* qkvB  = (const float*)d_in[5];
    const float* projW = (const float*)d_in[6];
    const float* projB = (const float*)d_in[7];
    float* out = (float*)d_out;

    float *qkv_buf, *attn_buf;
    cudaGetSymbolAddress((void**)&qkv_buf,  g_qkv);
    cudaGetSymbolAddress((void**)&attn_buf, g_attn);

    cudaFuncSetAttribute(attn_win, cudaFuncAttributeMaxDynamicSharedMemorySize, ATTN_SMEM);

    // 1) QKV = x @ qkv_kernel + qkv_bias        [32768, 3840]
    {
        dim3 grid(N_QKV / BN, S_TOK / BM);
        gemm_tf32<<<grid, 256>>>(x, qkvW, qkvB, qkv_buf, S_TOK, N_QKV, HID);
    }
    // 2) windowed attention (RoPE fused)        [32768, 1280]
    {
        attn_win<<<NWIN * NHEAD, 128, ATTN_SMEM>>>(qkv_buf, cosp, sinp, attn_buf);
    }
    // 3) out = attn @ proj_kernel + proj_bias   [32768, 1280]
    {
        dim3 grid(HID / BN, S_TOK / BM);
        gemm_tf32<<<grid, 256>>>(attn_buf, projW, projB, out, S_TOK, HID, HID);
    }
}

// round 3
// speedup vs baseline: 1.1547x; 1.1547x over previous
#include <cuda_runtime.h>
#include <cuda_bf16.h>
#include <cstdint>

// Problem constants
#define S_TOK   32768
#define HID     1280
#define NHEAD   16
#define DHEAD   80
#define WIN     64
#define NWIN    (S_TOK / WIN)
#define N_QKV   (3 * HID)

// Scratch (__device__ globals per allocation rules)
__device__ float g_xa  [(size_t)S_TOK * HID];     // x RNA-rounded
__device__ float g_qkv [(size_t)S_TOK * N_QKV];   // qkv output
__device__ float g_attn[(size_t)S_TOK * HID];     // attn out, RNA-rounded
__device__ float g_wqkv[(size_t)HID * N_QKV];     // qkvW RNA-rounded [1280,3840]
__device__ float g_wproj[(size_t)HID * HID];      // projW RNA-rounded [1280,1280]

__device__ __forceinline__ uint32_t f2tf32(float x) {
    uint32_t r;
    asm volatile("cvt.rna.tf32.f32 %0, %1;" : "=r"(r) : "f"(x));
    return r;
}
__device__ __forceinline__ uint32_t smem_u32(const void* p) {
    uint32_t a;
    asm("{ .reg .u64 t; cvta.to.shared.u64 t, %1; cvt.u32.u64 %0, t; }" : "=r"(a) : "l"(p));
    return a;
}
__device__ __forceinline__ void cp16(uint32_t dst, const void* src) {
    asm volatile("cp.async.cg.shared.global [%0], [%1], 16;" :: "r"(dst), "l"(src) : "memory");
}
#define CP_COMMIT() asm volatile("cp.async.commit_group;" ::: "memory")

// ---------------------------------------------------------------------------
// Legacy-tensor tf32 GEMM: C[M,N] = A[M,1280] @ B[1280,N] + bias[N]
// Block 128x128x32, 256 thr (8 warps = 4M x 2N, warp tile 32x64),
// cp.async double-buffer. Inputs must be pre-rounded to tf32 (RNA).
// ---------------------------------------------------------------------------
#define BM 128
#define BN 128
#define BK 32
#define AS_STRIDE 36          // (g*36) mod 32 = g*4 -> +t conflict-free
#define BS_STRIDE 136         // (t*136) mod 32 = t*8 -> +g conflict-free
#define A_FLOATS (BM * AS_STRIDE)          // 4608
#define B_FLOATS (BK * BS_STRIDE)          // 4352
#define STAGE_FLOATS (A_FLOATS + B_FLOATS) // 8960
#define GEMM_SMEM (2 * STAGE_FLOATS * 4)   // 71680 B

__global__ __launch_bounds__(256, 2)
void gemm_tc(const float* __restrict__ A, const float* __restrict__ B,
             const float* __restrict__ bias, float* __restrict__ C, int N)
{
    extern __shared__ float sm[];
    const int tid  = threadIdx.x;
    const int warp = tid >> 5;
    const int lane = tid & 31;
    const int g = lane >> 2;
    const int t = lane & 3;
    const int wm = (warp & 3) * 32;
    const int wn = (warp >> 2) * 64;
    const int block_m = blockIdx.y * BM;
    const int block_n = blockIdx.x * BN;

    const uint32_t sb = smem_u32(sm);

    float acc[2][8][4];
    #pragma unroll
    for (int i = 0; i < 2; i++)
        #pragma unroll
        for (int j = 0; j < 8; j++)
            #pragma unroll
            for (int r = 0; r < 4; r++) acc[i][j][r] = 0.f;

    const float* Abase = A + (size_t)block_m * HID;
    const float* Bbase = B + block_n;

    // fill stage s with K-chunk kidx (A: 1024 chunks, B: 1024 chunks)
    auto fill = [&](int kidx, int s) {
        const uint32_t sA = sb + s * STAGE_FLOATS * 4;
        const uint32_t sB = sA + A_FLOATS * 4;
        const int k0 = kidx * BK;
        #pragma unroll
        for (int ii = 0; ii < 4; ++ii) {          // A tile: 128 rows x 8 chunks
            const int id = tid + ii * 256;
            const int row = id >> 3, c = id & 7;
            cp16(sA + (row * AS_STRIDE + c * 4) * 4,
                 Abase + (size_t)row * HID + k0 + c * 4);
        }
        #pragma unroll
        for (int ii = 0; ii < 4; ++ii) {          // B tile: 32 rows x 32 chunks
            const int id = tid + ii * 256;
            const int row = id >> 5, c = id & 31;
            cp16(sB + (row * BS_STRIDE + c * 4) * 4,
                 Bbase + (size_t)(k0 + row) * N + c * 4);
        }
    };

    auto compute = [&](int s) {
        const float* As = sm + s * STAGE_FLOATS;
        const float* Bs = As + A_FLOATS;
        #pragma unroll
        for (int kk = 0; kk < BK; kk += 8) {
            uint32_t af[2][4];
            #pragma unroll
            for (int i = 0; i < 2; i++) {
                const int r0 = wm + i * 16;
                af[i][0] = __float_as_uint(As[(r0 + g    ) * AS_STRIDE + kk + t    ]);
                af[i][1] = __float_as_uint(As[(r0 + g + 8) * AS_STRIDE + kk + t    ]);
                af[i][2] = __float_as_uint(As[(r0 + g    ) * AS_STRIDE + kk + t + 4]);
                af[i][3] = __float_as_uint(As[(r0 + g + 8) * AS_STRIDE + kk + t + 4]);
            }
            uint32_t bf[8][2];
            #pragma unroll
            for (int j = 0; j < 8; j++) {
                const int c0 = wn + j * 8;
                bf[j][0] = __float_as_uint(Bs[(kk + t    ) * BS_STRIDE + c0 + g]);
                bf[j][1] = __float_as_uint(Bs[(kk + t + 4) * BS_STRIDE + c0 + g]);
            }
            #pragma unroll
            for (int i = 0; i < 2; i++)
                #pragma unroll
                for (int j = 0; j < 8; j++) {
                    asm volatile(
                        "mma.sync.aligned.m16n8k8.row.col.f32.tf32.tf32.f32 "
                        "{%0,%1,%2,%3}, {%4,%5,%6,%7}, {%8,%9}, {%0,%1,%2,%3};\n"
                        : "+f"(acc[i][j][0]), "+f"(acc[i][j][1]),
                          "+f"(acc[i][j][2]), "+f"(acc[i][j][3])
                        : "r"(af[i][0]), "r"(af[i][1]), "r"(af[i][2]), "r"(af[i][3]),
                          "r"(bf[j][0]), "r"(bf[j][1]));
                }
        }
    };

    const int nIter = HID / BK;   // 40
    fill(0, 0); CP_COMMIT();
    for (int it = 0; it < nIter; ++it) {
        if (it + 1 < nIter) {
            fill(it + 1, (it + 1) & 1); CP_COMMIT();
            asm volatile("cp.async.wait_group 1;" ::: "memory");
        } else {
            asm volatile("cp.async.wait_group 0;" ::: "memory");
        }
        __syncthreads();
        compute(it & 1);
        __syncthreads();
    }

    // epilogue: bias + store (each thread: 2x8 pairs of 2 contiguous floats)
    #pragma unroll
    for (int i = 0; i < 2; i++) {
        #pragma unroll
        for (int j = 0; j < 8; j++) {
            const int r = block_m + wm + i * 16 + g;
            const int c = block_n + wn + j * 8 + t * 2;
            const float b0 = bias[c], b1 = bias[c + 1];
            float2 v0 = make_float2(acc[i][j][0] + b0, acc[i][j][1] + b1);
            float2 v1 = make_float2(acc[i][j][2] + b0, acc[i][j][3] + b1);
            *(float2*)&C[(size_t)r       * N + c] = v0;
            *(float2*)&C[(size_t)(r + 8) * N + c] = v1;
        }
    }
}

// ---------------------------------------------------------------------------
// RNA round to tf32 (elementwise, vectorized)
// ---------------------------------------------------------------------------
__global__ void rna_convert(const float4* __restrict__ in, float4* __restrict__ out, int n4)
{
    const int i = blockIdx.x * 256 + threadIdx.x;
    if (i < n4) {
        float4 v = in[i];
        v.x = __uint_as_float(f2tf32(v.x));
        v.y = __uint_as_float(f2tf32(v.y));
        v.z = __uint_as_float(f2tf32(v.z));
        v.w = __uint_as_float(f2tf32(v.w));
        out[i] = v;
    }
}

// ---------------------------------------------------------------------------
// Windowed attention, one block per (window, head). RNA on output store.
// ---------------------------------------------------------------------------
#define P_STRIDE 65
#define ATTN_SMEM ((3 * 64 * 80 + 64 * P_STRIDE) * 4)

__global__ __launch_bounds__(128, 2)
void attn_win(const float* __restrict__ qkv,
              const float* __restrict__ cosp, const float* __restrict__ sinp,
              float* __restrict__ out)
{
    extern __shared__ float sh[];
    float* qs = sh;
    float* ks = sh + 64 * 80;
    float* vs = sh + 2 * 64 * 80;
    float* p  = sh + 3 * 64 * 80;

    const int w = blockIdx.x >> 4;
    const int h = blockIdx.x & 15;
    const int tid = threadIdx.x;

    for (int idx = tid; idx < 64 * 40; idx += 128) {
        const int i = idx / 40;
        const int d = idx - i * 40;
        const int srow = w * WIN + i;
        const float c1 = cosp[srow * DHEAD + d];
        const float s1 = sinp[srow * DHEAD + d];
        const float c2 = cosp[srow * DHEAD + d + 40];
        const float s2 = sinp[srow * DHEAD + d + 40];
        const float* base = qkv + (size_t)srow * N_QKV + h * DHEAD;
        const float q1 = base[d],       q2 = base[d + 40];
        const float k1 = base[HID + d], k2 = base[HID + d + 40];
        qs[i * 80 + d]      = q1 * c1 - q2 * s1;
        qs[i * 80 + d + 40] = q2 * c2 + q1 * s2;
        ks[i * 80 + d]      = k1 * c1 - k2 * s1;
        ks[i * 80 + d + 40] = k2 * c2 + k1 * s2;
    }
    for (int idx = tid; idx < 64 * 80; idx += 128) {
        const int i = idx / 80;
        const int d = idx - i * 80;
        vs[idx] = qkv[(size_t)(w * WIN + i) * N_QKV + 2 * HID + h * DHEAD + d];
    }
    __syncthreads();

    const int ti = tid >> 3;
    const int tj = tid & 7;
    const int i0 = ti * 4;
    const int j0 = tj * 8;
    float sc[4][8];
    #pragma unroll
    for (int r = 0; r < 4; r++)
        #pragma unroll
        for (int c = 0; c < 8; c++) sc[r][c] = 0.f;

    for (int d = 0; d < DHEAD; d++) {
        float qv[4], kv[8];
        #pragma unroll
        for (int r = 0; r < 4; r++) qv[r] = qs[(i0 + r) * 80 + d];
        #pragma unroll
        for (int c = 0; c < 8; c++) kv[c] = ks[(j0 + c) * 80 + d];
        #pragma unroll
        for (int r = 0; r < 4; r++)
            #pragma unroll
            for (int c = 0; c < 8; c++) sc[r][c] = fmaf(qv[r], kv[c], sc[r][c]);
    }
    const float scale = 0.11180339887498949f;
    #pragma unroll
    for (int r = 0; r < 4; r++)
        #pragma unroll
        for (int c = 0; c < 8; c++)
            p[(i0 + r) * P_STRIDE + j0 + c] = sc[r][c] * scale;
    __syncthreads();

    if (tid < 64) {
        float* row = p + tid * P_STRIDE;
        float m = -1e30f;
        #pragma unroll 8
        for (int j = 0; j < 64; j++) m = fmaxf(m, row[j]);
        float s = 0.f;
        #pragma unroll 8
        for (int j = 0; j < 64; j++) { float e = __expf(row[j] - m); row[j] = e; s += e; }
        const float inv = 1.f / s;
        #pragma unroll 8
        for (int j = 0; j < 64; j++) row[j] *= inv;
    }
    __syncthreads();

    const int tc = tid & 7;
    const int c0 = tc * 10;
    float o[4][10];
    #pragma unroll
    for (int r = 0; r < 4; r++)
        #pragma unroll
        for (int c = 0; c < 10; c++) o[r][c] = 0.f;

    for (int j = 0; j < 64; j++) {
        float pv[4], vv[10];
        #pragma unroll
        for (int r = 0; r < 4; r++) pv[r] = p[(i0 + r) * P_STRIDE + j];
        #pragma unroll
        for (int c = 0; c < 10; c++) vv[c] = vs[j * 80 + c0 + c];
        #pragma unroll
        for (int r = 0; r < 4; r++)
            #pragma unroll
            for (int c = 0; c < 10; c++) o[r][c] = fmaf(pv[r], vv[c], o[r][c]);
    }
    #pragma unroll
    for (int r = 0; r < 4; r++) {
        const size_t row = (size_t)(w * WIN + i0 + r) * HID + h * DHEAD + c0;
        #pragma unroll
        for (int c = 0; c < 10; c++)
            out[row + c] = __uint_as_float(f2tf32(o[r][c]));   // RNA: feeds GEMM2
    }
}

// ---------------------------------------------------------------------------
extern "C" void kernel_launch(void* const* d_in, const int* in_sizes, int n_in,
                              void* d_out, int out_size)
{
    const float* x     = (const float*)d_in[0];
    const float* cosp  = (const float*)d_in[1];
    const float* sinp  = (const float*)d_in[2];
    const float* qkvW  = (const float*)d_in[4];
    const float* qkvB  = (const float*)d_in[5];
    const float* projW = (const float*)d_in[6];
    const float* projB = (const float*)d_in[7];
    float* out = (float*)d_out;

    float *xa, *qkv, *attn, *wqkv, *wproj;
    cudaGetSymbolAddress((void**)&xa,    g_xa);
    cudaGetSymbolAddress((void**)&qkv,   g_qkv);
    cudaGetSymbolAddress((void**)&attn,  g_attn);
    cudaGetSymbolAddress((void**)&wqkv,  g_wqkv);
    cudaGetSymbolAddress((void**)&wproj, g_wproj);

    cudaFuncSetAttribute(gemm_tc,  cudaFuncAttributeMaxDynamicSharedMemorySize, GEMM_SMEM);
    cudaFuncSetAttribute(attn_win, cudaFuncAttributeMaxDynamicSharedMemorySize, ATTN_SMEM);

    // RNA pre-rounding (so GEMM truncation == RNA rounding)
    rna_convert<<<(S_TOK * HID / 4 + 255) / 256, 256>>>((const float4*)x, (float4*)xa, S_TOK * HID / 4);
    rna_convert<<<(HID * N_QKV / 4 + 255) / 256, 256>>>((const float4*)qkvW, (float4*)wqkv, HID * N_QKV / 4);
    rna_convert<<<(HID * HID / 4 + 255) / 256, 256>>>((const float4*)projW, (float4*)wproj, HID * HID / 4);

    // 1) QKV = x @ qkvW + b
    gemm_tc<<<dim3(N_QKV / BN, S_TOK / BM), 256, GEMM_SMEM>>>(xa, wqkv, qkvB, qkv, N_QKV);
    // 2) windowed attention (RoPE fused)
    attn_win<<<NWIN * NHEAD, 128, ATTN_SMEM>>>(qkv, cosp, sinp, attn);
    // 3) out = attn @ projW + b
    gemm_tc<<<dim3(HID / BN, S_TOK / BM), 256, GEMM_SMEM>>>(attn, wproj, projB, out, HID);
}

// round 4
// speedup vs baseline: 1.3892x; 1.2031x over previous
#include <cuda_runtime.h>
#include <cuda_bf16.h>
#include <cstdint>

// Problem constants
#define S_TOK   32768
#define HID     1280
#define NHEAD   16
#define DHEAD   80
#define WIN     64
#define NWIN    (S_TOK / WIN)
#define N_QKV   (3 * HID)

// Scratch (__device__ globals per allocation rules)
__device__ float g_xa  [(size_t)S_TOK * HID];     // x RNA-rounded
__device__ float g_qkv [(size_t)S_TOK * N_QKV];   // qkv output
__device__ float g_attn[(size_t)S_TOK * HID];     // attn out, RNA-rounded
__device__ float g_wqkv[(size_t)HID * N_QKV];     // qkvW RNA-rounded
__device__ float g_wproj[(size_t)HID * HID];      // projW RNA-rounded

__device__ __forceinline__ uint32_t f2tf32(float x) {
    uint32_t r;
    asm volatile("cvt.rna.tf32.f32 %0, %1;" : "=r"(r) : "f"(x));
    return r;
}
__device__ __forceinline__ uint32_t smem_u32(const void* p) {
    uint32_t a;
    asm("{ .reg .u64 t; cvta.to.shared.u64 t, %1; cvt.u32.u64 %0, t; }" : "=r"(a) : "l"(p));
    return a;
}
__device__ __forceinline__ void cp16(uint32_t dst, const void* src) {
    asm volatile("cp.async.cg.shared.global [%0], [%1], 16;" :: "r"(dst), "l"(src) : "memory");
}
#define CP_COMMIT() asm volatile("cp.async.commit_group;" ::: "memory")

// ---------------------------------------------------------------------------
// Legacy-tensor tf32 GEMM: C[M,N] = A[M,1280] @ B[1280,N] + bias[N]
// Block 128x128x32, 256 thr (8 warps = 4M x 2N, warp tile 32x64),
// 3-stage cp.async pipeline, ONE __syncthreads per K-iteration.
// Inputs must be pre-rounded to tf32 (RNA).
// ---------------------------------------------------------------------------
#define BM 128
#define BN 128
#define BK 32
#define NSTAGE 3
#define AS_STRIDE 36          // (g*36) mod 32 = g*4 -> +t conflict-free
#define BS_STRIDE 136         // (t*136) mod 32 = t*8 -> +g conflict-free
#define A_FLOATS (BM * AS_STRIDE)          // 4608
#define B_FLOATS (BK * BS_STRIDE)          // 4352
#define STAGE_FLOATS (A_FLOATS + B_FLOATS) // 8960
#define GEMM_SMEM (NSTAGE * STAGE_FLOATS * 4)   // 107520 B

__global__ __launch_bounds__(256, 2)
void gemm_tc(const float* __restrict__ A, const float* __restrict__ B,
             const float* __restrict__ bias, float* __restrict__ C, int N)
{
    extern __shared__ float sm[];
    const int tid  = threadIdx.x;
    const int warp = tid >> 5;
    const int lane = tid & 31;
    const int g = lane >> 2;
    const int t = lane & 3;
    const int wm = (warp & 3) * 32;
    const int wn = (warp >> 2) * 64;
    const int block_m = blockIdx.y * BM;
    const int block_n = blockIdx.x * BN;

    const uint32_t sb = smem_u32(sm);

    float acc[2][8][4];
    #pragma unroll
    for (int i = 0; i < 2; i++)
        #pragma unroll
        for (int j = 0; j < 8; j++)
            #pragma unroll
            for (int r = 0; r < 4; r++) acc[i][j][r] = 0.f;

    const float* Abase = A + (size_t)block_m * HID;
    const float* Bbase = B + block_n;

    auto fill = [&](int kidx, int s) {
        const uint32_t sA = sb + s * STAGE_FLOATS * 4;
        const uint32_t sB = sA + A_FLOATS * 4;
        const int k0 = kidx * BK;
        #pragma unroll
        for (int ii = 0; ii < 4; ++ii) {          // A: 128 rows x 8 chunks
            const int id = tid + ii * 256;
            const int row = id >> 3, c = id & 7;
            cp16(sA + (row * AS_STRIDE + c * 4) * 4,
                 Abase + (size_t)row * HID + k0 + c * 4);
        }
        #pragma unroll
        for (int ii = 0; ii < 4; ++ii) {          // B: 32 rows x 32 chunks
            const int id = tid + ii * 256;
            const int row = id >> 5, c = id & 31;
            cp16(sB + (row * BS_STRIDE + c * 4) * 4,
                 Bbase + (size_t)(k0 + row) * N + c * 4);
        }
    };

    auto compute = [&](int s) {
        const float* As = sm + s * STAGE_FLOATS;
        const float* Bs = As + A_FLOATS;
        #pragma unroll
        for (int kk = 0; kk < BK; kk += 8) {
            uint32_t af[2][4];
            #pragma unroll
            for (int i = 0; i < 2; i++) {
                const int r0 = wm + i * 16;
                af[i][0] = __float_as_uint(As[(r0 + g    ) * AS_STRIDE + kk + t    ]);
                af[i][1] = __float_as_uint(As[(r0 + g + 8) * AS_STRIDE + kk + t    ]);
                af[i][2] = __float_as_uint(As[(r0 + g    ) * AS_STRIDE + kk + t + 4]);
                af[i][3] = __float_as_uint(As[(r0 + g + 8) * AS_STRIDE + kk + t + 4]);
            }
            uint32_t bf[8][2];
            #pragma unroll
            for (int j = 0; j < 8; j++) {
                const int c0 = wn + j * 8;
                bf[j][0] = __float_as_uint(Bs[(kk + t    ) * BS_STRIDE + c0 + g]);
                bf[j][1] = __float_as_uint(Bs[(kk + t + 4) * BS_STRIDE + c0 + g]);
            }
            #pragma unroll
            for (int i = 0; i < 2; i++)
                #pragma unroll
                for (int j = 0; j < 8; j++) {
                    asm volatile(
                        "mma.sync.aligned.m16n8k8.row.col.f32.tf32.tf32.f32 "
                        "{%0,%1,%2,%3}, {%4,%5,%6,%7}, {%8,%9}, {%0,%1,%2,%3};\n"
                        : "+f"(acc[i][j][0]), "+f"(acc[i][j][1]),
                          "+f"(acc[i][j][2]), "+f"(acc[i][j][3])
                        : "r"(af[i][0]), "r"(af[i][1]), "r"(af[i][2]), "r"(af[i][3]),
                          "r"(bf[j][0]), "r"(bf[j][1]));
                }
        }
    };

    const int nIter = HID / BK;   // 40

    // prologue: fill stages 0,1
    fill(0, 0); CP_COMMIT();
    fill(1, 1); CP_COMMIT();

    for (int it = 0; it < nIter; ++it) {
        if (it + 2 < nIter) asm volatile("cp.async.wait_group 1;" ::: "memory");
        else                asm volatile("cp.async.wait_group 0;" ::: "memory");
        __syncthreads();     // stage it%NSTAGE ready; stage (it+2)%NSTAGE free
        if (it + 2 < nIter) {
            fill(it + 2, (it + 2) % NSTAGE);
            CP_COMMIT();
        }
        compute(it % NSTAGE);
    }

    // epilogue: bias + store
    #pragma unroll
    for (int i = 0; i < 2; i++) {
        #pragma unroll
        for (int j = 0; j < 8; j++) {
            const int r = block_m + wm + i * 16 + g;
            const int c = block_n + wn + j * 8 + t * 2;
            const float b0 = bias[c], b1 = bias[c + 1];
            float2 v0 = make_float2(acc[i][j][0] + b0, acc[i][j][1] + b1);
            float2 v1 = make_float2(acc[i][j][2] + b0, acc[i][j][3] + b1);
            *(float2*)&C[(size_t)r       * N + c] = v0;
            *(float2*)&C[(size_t)(r + 8) * N + c] = v1;
        }
    }
}

// ---------------------------------------------------------------------------
// RNA round to tf32 (elementwise, vectorized)
// ---------------------------------------------------------------------------
__global__ void rna_convert(const float4* __restrict__ in, float4* __restrict__ out, int n4)
{
    const int i = blockIdx.x * 256 + threadIdx.x;
    if (i < n4) {
        float4 v = in[i];
        v.x = __uint_as_float(f2tf32(v.x));
        v.y = __uint_as_float(f2tf32(v.y));
        v.z = __uint_as_float(f2tf32(v.z));
        v.w = __uint_as_float(f2tf32(v.w));
        out[i] = v;
    }
}

// ---------------------------------------------------------------------------
// Windowed attention, one block per (window, head).
// Row stride 81: kills the mod-32 bank aliasing of stride 80
// (K loads 8-way -> 2-way, Q loads 4-way -> conflict-free).
// ---------------------------------------------------------------------------
#define QKV_STRIDE 81
#define P_STRIDE 65
#define ATTN_SMEM ((3 * 64 * QKV_STRIDE + 64 * P_STRIDE) * 4)

__global__ __launch_bounds__(128, 2)
void attn_win(const float* __restrict__ qkv,
              const float* __restrict__ cosp, const float* __restrict__ sinp,
              float* __restrict__ out)
{
    extern __shared__ float sh[];
    float* qs = sh;
    float* ks = sh + 64 * QKV_STRIDE;
    float* vs = sh + 2 * 64 * QKV_STRIDE;
    float* p  = sh + 3 * 64 * QKV_STRIDE;

    const int w = blockIdx.x >> 4;
    const int h = blockIdx.x & 15;
    const int tid = threadIdx.x;

    for (int idx = tid; idx < 64 * 40; idx += 128) {
        const int i = idx / 40;
        const int d = idx - i * 40;
        const int srow = w * WIN + i;
        const float c1 = cosp[srow * DHEAD + d];
        const float s1 = sinp[srow * DHEAD + d];
        const float c2 = cosp[srow * DHEAD + d + 40];
        const float s2 = sinp[srow * DHEAD + d + 40];
        const float* base = qkv + (size_t)srow * N_QKV + h * DHEAD;
        const float q1 = base[d],       q2 = base[d + 40];
        const float k1 = base[HID + d], k2 = base[HID + d + 40];
        qs[i * QKV_STRIDE + d]      = q1 * c1 - q2 * s1;
        qs[i * QKV_STRIDE + d + 40] = q2 * c2 + q1 * s2;
        ks[i * QKV_STRIDE + d]      = k1 * c1 - k2 * s1;
        ks[i * QKV_STRIDE + d + 40] = k2 * c2 + k1 * s2;
    }
    for (int idx = tid; idx < 64 * 80; idx += 128) {
        const int i = idx / 80;
        const int d = idx - i * 80;
        vs[i * QKV_STRIDE + d] = qkv[(size_t)(w * WIN + i) * N_QKV + 2 * HID + h * DHEAD + d];
    }
    __syncthreads();

    const int ti = tid >> 3;
    const int tj = tid & 7;
    const int i0 = ti * 4;
    const int j0 = tj * 8;
    float sc[4][8];
    #pragma unroll
    for (int r = 0; r < 4; r++)
        #pragma unroll
        for (int c = 0; c < 8; c++) sc[r][c] = 0.f;

    for (int d = 0; d < DHEAD; d++) {
        float qv[4], kv[8];
        #pragma unroll
        for (int r = 0; r < 4; r++) qv[r] = qs[(i0 + r) * QKV_STRIDE + d];
        #pragma unroll
        for (int c = 0; c < 8; c++) kv[c] = ks[(j0 + c) * QKV_STRIDE + d];
        #pragma unroll
        for (int r = 0; r < 4; r++)
            #pragma unroll
            for (int c = 0; c < 8; c++) sc[r][c] = fmaf(qv[r], kv[c], sc[r][c]);
    }
    const float scale = 0.11180339887498949f;
    #pragma unroll
    for (int r = 0; r < 4; r++)
        #pragma unroll
        for (int c = 0; c < 8; c++)
            p[(i0 + r) * P_STRIDE + j0 + c] = sc[r][c] * scale;
    __syncthreads();

    if (tid < 64) {
        float* row = p + tid * P_STRIDE;
        float m = -1e30f;
        #pragma unroll 8
        for (int j = 0; j < 64; j++) m = fmaxf(m, row[j]);
        float s = 0.f;
        #pragma unroll 8
        for (int j = 0; j < 64; j++) { float e = __expf(row[j] - m); row[j] = e; s += e; }
        const float inv = 1.f / s;
        #pragma unroll 8
        for (int j = 0; j < 64; j++) row[j] *= inv;
    }
    __syncthreads();

    const int tc = tid & 7;
    const int c0 = tc * 10;
    float o[4][10];
    #pragma unroll
    for (int r = 0; r < 4; r++)
        #pragma unroll
        for (int c = 0; c < 10; c++) o[r][c] = 0.f;

    for (int j = 0; j < 64; j++) {
        float pv[4], vv[10];
        #pragma unroll
        for (int r = 0; r < 4; r++) pv[r] = p[(i0 + r) * P_STRIDE + j];
        #pragma unroll
        for (int c = 0; c < 10; c++) vv[c] = vs[j * QKV_STRIDE + c0 + c];
        #pragma unroll
        for (int r = 0; r < 4; r++)
            #pragma unroll
            for (int c = 0; c < 10; c++) o[r][c] = fmaf(pv[r], vv[c], o[r][c]);
    }
    #pragma unroll
    for (int r = 0; r < 4; r++) {
        const size_t row = (size_t)(w * WIN + i0 + r) * HID + h * DHEAD + c0;
        #pragma unroll
        for (int c = 0; c < 10; c++)
            out[row + c] = __uint_as_float(f2tf32(o[r][c]));   // RNA: feeds GEMM2
    }
}

// ---------------------------------------------------------------------------
extern "C" void kernel_launch(void* const* d_in, const int* in_sizes, int n_in,
                              void* d_out, int out_size)
{
    const float* x     = (const float*)d_in[0];
    const float* cosp  = (const float*)d_in[1];
    const float* sinp  = (const float*)d_in[2];
    const float* qkvW  = (const float*)d_in[4];
    const float* qkvB  = (const float*)d_in[5];
    const float* projW = (const float*)d_in[6];
    const float* projB = (const float*)d_in[7];
    float* out = (float*)d_out;

    float *xa, *qkv, *attn, *wqkv, *wproj;
    cudaGetSymbolAddress((void**)&xa,    g_xa);
    cudaGetSymbolAddress((void**)&qkv,   g_qkv);
    cudaGetSymbolAddress((void**)&attn,  g_attn);
    cudaGetSymbolAddress((void**)&wqkv,  g_wqkv);
    cudaGetSymbolAddress((void**)&wproj, g_wproj);

    cudaFuncSetAttribute(gemm_tc,  cudaFuncAttributeMaxDynamicSharedMemorySize, GEMM_SMEM);
    cudaFuncSetAttribute(attn_win, cudaFuncAttributeMaxDynamicSharedMemorySize, ATTN_SMEM);

    // RNA pre-rounding (GEMM truncation then == RNA rounding)
    rna_convert<<<(S_TOK * HID / 4 + 255) / 256, 256>>>((const float4*)x, (float4*)xa, S_TOK * HID / 4);
    rna_convert<<<(HID * N_QKV / 4 + 255) / 256, 256>>>((const float4*)qkvW, (float4*)wqkv, HID * N_QKV / 4);
    rna_convert<<<(HID * HID / 4 + 255) / 256, 256>>>((const float4*)projW, (float4*)wproj, HID * HID / 4);

    // 1) QKV = x @ qkvW + b
    gemm_tc<<<dim3(N_QKV / BN, S_TOK / BM), 256, GEMM_SMEM>>>(xa, wqkv, qkvB, qkv, N_QKV);
    // 2) windowed attention (RoPE fused)
    attn_win<<<NWIN * NHEAD, 128, ATTN_SMEM>>>(qkv, cosp, sinp, attn);
    // 3) out = attn @ projW + b
    gemm_tc<<<dim3(HID / BN, S_TOK / BM), 256, GEMM_SMEM>>>(attn, wproj, projB, out, HID);
}